// round 13
// baseline (speedup 1.0000x reference)
#include <cuda_runtime.h>
#include <cstdint>

#define D_DIM 25000
#define B_DIM 64
#define K_DIM 16
#define H_DIM 128
#define E_DIM 256
#define Z_DIM 32

#define NBLK   592              // 148 SMs x 4 CTAs -> one wave
#define NC4    6250             // 4-d chunks
#define RBIG   330              // 330 CTAs take 11 chunks, 262 take 10

// ---- scratch (device globals; no allocations allowed) ----
__device__ float c_part[NBLK * B_DIM * K_DIM];  // per-block partial pooled c

// pack two fp32 -> bf16x2 {lo=a, hi=b}
__device__ __forceinline__ unsigned pkbf16(float a, float b) {
    unsigned r;
    asm("cvt.rn.bf16x2.f32 %0, %1, %2;" : "=r"(r) : "f"(b), "f"(a));
    return r;
}
__device__ __forceinline__ float bflo(unsigned p) { return __uint_as_float(p << 16); }
__device__ __forceinline__ float bfhi(unsigned p) { return __uint_as_float(p & 0xffff0000u); }
__device__ __forceinline__ unsigned relu2(unsigned a) {
    unsigned r;
    asm("max.bf16x2 %0, %1, %2;" : "=r"(r) : "r"(a), "r"(0u));
    return r;
}

#define MMA(C, a0, a1, a2, a3, b0, b1)                                     \
    asm("mma.sync.aligned.m16n8k16.row.col.f32.bf16.bf16.f32 "             \
        "{%0,%1,%2,%3}, {%4,%5,%6,%7}, {%8,%9}, {%0,%1,%2,%3};"            \
        : "+f"((C)[0]), "+f"((C)[1]), "+f"((C)[2]), "+f"((C)[3])           \
        : "r"(a0), "r"(a1), "r"(a2), "r"(a3), "r"(b0), "r"(b1))

// ---------------------------------------------------------------------------
// Kernel 1: fused g-compute + tensor-core stage-2 + masked pooling.
// Block = 128 thr = 4 warps. Warp w owns batches [16w,16w+16); warps share d.
// Per 4-d chunk: stage fe/fb/x/mask (vectorized), compute g[4][128] in smem,
// then per d build A = relu(x*w0+g) in-fragment (bf16) and run 4 MMAs/ks:
// Ca += a*W2hi, Cb += a*W2lo (split-bf16 weight compensation).
// ---------------------------------------------------------------------------
__global__ __launch_bounds__(128, 4)
void k_main(const float* __restrict__ x, const int* __restrict__ mask,
            const float* __restrict__ W1, const float* __restrict__ W2,
            const float* __restrict__ b2,
            const float* __restrict__ fe, const float* __restrict__ fb,
            const float* __restrict__ b1)
{
    __shared__ __align__(16) float W1s[18 * H_DIM]; // 9 KB  (row 0 = w0)
    __shared__ __align__(16) float b1s[H_DIM];
    __shared__ __align__(16) uint2 wloS[16 * 32];   // W2-lo frags, 4 KB
    __shared__ __align__(16) float gs[4 * H_DIM];   // 2 KB
    __shared__ __align__(16) float xs[4][B_DIM];    // 1 KB
    __shared__ __align__(16) float ms[4][B_DIM];    // 1 KB
    __shared__ __align__(16) float fes[4 * K_DIM];  // 256 B
    __shared__ float fbs[4];

    const int t    = threadIdx.x;
    const int lane = t & 31;
    const int wrp  = t >> 5;
    const int g_l  = lane >> 2;     // 0..7  (row group)
    const int tt   = lane & 3;      // 0..3  (thread-in-group)
    const int bg   = wrp * 16;      // batch base of this warp

    // ---- one-time staging ----
    for (int i = t; i < 18 * H_DIM; i += 128) W1s[i] = W1[i];
    if (t < H_DIM) b1s[t] = b1[t];

    // W2 fragments: hi in regs (all warps), lo into smem table (warp 0)
    unsigned whi[8][2][2];
#pragma unroll
    for (int ks = 0; ks < 8; ks++) {
#pragma unroll
        for (int nh = 0; nh < 2; nh++) {
            const int j0 = ks * 16 + 2 * tt;
            const int n  = nh * 8 + g_l;
            float w00 = W2[(j0    ) * K_DIM + n];
            float w01 = W2[(j0 + 1) * K_DIM + n];
            float w10 = W2[(j0 + 8) * K_DIM + n];
            float w11 = W2[(j0 + 9) * K_DIM + n];
            unsigned h0 = pkbf16(w00, w01);
            unsigned h1 = pkbf16(w10, w11);
            whi[ks][nh][0] = h0;
            whi[ks][nh][1] = h1;
            if (wrp == 0) {
                unsigned l0 = pkbf16(w00 - bflo(h0), w01 - bfhi(h0));
                unsigned l1 = pkbf16(w10 - bflo(h1), w11 - bfhi(h1));
                wloS[(ks * 2 + nh) * 32 + lane] = make_uint2(l0, l1);
            }
        }
    }
    const float b2r0 = b2[2 * tt],     b2r1 = b2[2 * tt + 1];
    const float b2r2 = b2[8 + 2 * tt], b2r3 = b2[8 + 2 * tt + 1];

    float acc[8];
#pragma unroll
    for (int i = 0; i < 8; i++) acc[i] = 0.f;

    __syncthreads();

    // balanced 4-d chunk partition: 6250 = 330*11 + 262*10
    int cnt, base;
    if (blockIdx.x < RBIG) { cnt = 11; base = blockIdx.x * 11; }
    else                   { cnt = 10; base = RBIG * 11 + (blockIdx.x - RBIG) * 10; }

    for (int ci = 0; ci < cnt; ci++) {
        const int d0 = (base + ci) * 4;

        // ---- stage fe/fb/x/mask for 4 d's (vectorized; d0 % 4 == 0) ----
        if (t < 64) {
            fes[t] = fe[d0 * K_DIM + t];                     // 4 rows x 16
            const float4 xv = *(const float4*)(x + t * D_DIM + d0);
            xs[0][t] = xv.x; xs[1][t] = xv.y; xs[2][t] = xv.z; xs[3][t] = xv.w;
        } else {
            const int b = t - 64;
            const int4 mv = *(const int4*)(mask + b * D_DIM + d0);
            ms[0][b] = (float)mv.x; ms[1][b] = (float)mv.y;
            ms[2][b] = (float)mv.z; ms[3][b] = (float)mv.w;
            if (b < 4) fbs[b] = fb[d0 + b];
        }
        __syncthreads();

        // ---- compute g[4][128] in smem: j = t ----
        {
            const int j = t;
#pragma unroll
            for (int dq = 0; dq < 4; dq++) {
                float a = b1s[j] + fbs[dq] * W1s[17 * H_DIM + j];
                const float* fr = fes + dq * K_DIM;
#pragma unroll
                for (int i = 0; i < K_DIM; i++)
                    a = fmaf(fr[i], W1s[(1 + i) * H_DIM + j], a);
                gs[dq * H_DIM + j] = a;
            }
        }
        __syncthreads();

        // ---- MMA phase over 4 d's ----
        for (int dq = 0; dq < 4; dq++) {
            const float* gsd = gs + dq * H_DIM;
            const float x0 = xs[dq][bg + g_l];
            const float x1 = xs[dq][bg + g_l + 8];
            const float m0 = ms[dq][bg + g_l];
            const float m1 = ms[dq][bg + g_l + 8];

            float Ca[2][4], Cb[2][4];
#pragma unroll
            for (int nh = 0; nh < 2; nh++)
#pragma unroll
                for (int i = 0; i < 4; i++) { Ca[nh][i] = 0.f; Cb[nh][i] = 0.f; }

#pragma unroll
            for (int ks = 0; ks < 8; ks++) {
                const int j0 = ks * 16 + 2 * tt;
                const float2 gA = *(const float2*)(gsd + j0);
                const float2 gB = *(const float2*)(gsd + j0 + 8);
                const float2 wA = *(const float2*)(W1s + j0);       // row 0 = w0
                const float2 wB = *(const float2*)(W1s + j0 + 8);

                const float h00 = fmaf(x0, wA.x, gA.x);
                const float h01 = fmaf(x0, wA.y, gA.y);
                const float h02 = fmaf(x0, wB.x, gB.x);
                const float h03 = fmaf(x0, wB.y, gB.y);
                const float h10 = fmaf(x1, wA.x, gA.x);
                const float h11 = fmaf(x1, wA.y, gA.y);
                const float h12 = fmaf(x1, wB.x, gB.x);
                const float h13 = fmaf(x1, wB.y, gB.y);

                const unsigned a0 = relu2(pkbf16(h00, h01));
                const unsigned a1 = relu2(pkbf16(h10, h11));
                const unsigned a2 = relu2(pkbf16(h02, h03));
                const unsigned a3 = relu2(pkbf16(h12, h13));

#pragma unroll
                for (int nh = 0; nh < 2; nh++) {
                    const uint2 wlo = wloS[(ks * 2 + nh) * 32 + lane];
                    MMA(Ca[nh], a0, a1, a2, a3, whi[ks][nh][0], whi[ks][nh][1]);
                    MMA(Cb[nh], a0, a1, a2, a3, wlo.x, wlo.y);
                }
            }

            // epilogue: relu(s + b2) * mask, pooled
            acc[0] = fmaf(m0, fmaxf(Ca[0][0] + Cb[0][0] + b2r0, 0.f), acc[0]);
            acc[1] = fmaf(m0, fmaxf(Ca[0][1] + Cb[0][1] + b2r1, 0.f), acc[1]);
            acc[2] = fmaf(m1, fmaxf(Ca[0][2] + Cb[0][2] + b2r0, 0.f), acc[2]);
            acc[3] = fmaf(m1, fmaxf(Ca[0][3] + Cb[0][3] + b2r1, 0.f), acc[3]);
            acc[4] = fmaf(m0, fmaxf(Ca[1][0] + Cb[1][0] + b2r2, 0.f), acc[4]);
            acc[5] = fmaf(m0, fmaxf(Ca[1][1] + Cb[1][1] + b2r3, 0.f), acc[5]);
            acc[6] = fmaf(m1, fmaxf(Ca[1][2] + Cb[1][2] + b2r2, 0.f), acc[6]);
            acc[7] = fmaf(m1, fmaxf(Ca[1][3] + Cb[1][3] + b2r3, 0.f), acc[7]);
        }
        __syncthreads();   // protect smem before next staging
    }

    // per-block partial store; warps own disjoint batches
    float* cp = c_part + blockIdx.x * (B_DIM * K_DIM);
    const int b0r = bg + g_l, b1r = bg + g_l + 8;
    cp[b0r * K_DIM +     2 * tt    ] = acc[0];
    cp[b0r * K_DIM +     2 * tt + 1] = acc[1];
    cp[b1r * K_DIM +     2 * tt    ] = acc[2];
    cp[b1r * K_DIM +     2 * tt + 1] = acc[3];
    cp[b0r * K_DIM + 8 + 2 * tt    ] = acc[4];
    cp[b0r * K_DIM + 8 + 2 * tt + 1] = acc[5];
    cp[b1r * K_DIM + 8 + 2 * tt    ] = acc[6];
    cp[b1r * K_DIM + 8 + 2 * tt + 1] = acc[7];
}

// ---------------------------------------------------------------------------
// Kernel 2: fused partial-reduce + encoder MLP + split (mu||logvar) output.
// ---------------------------------------------------------------------------
__global__ void k_enc(const float* __restrict__ We1, const float* __restrict__ be1,
                      const float* __restrict__ We2, const float* __restrict__ be2,
                      float* __restrict__ out)
{
    __shared__ float red16[16][17];
    __shared__ float cb[K_DIM];
    __shared__ float hE[E_DIM];
    __shared__ float red[256];
    const int b = blockIdx.x, t = threadIdx.x;   // 256 threads

    {   // deterministic reduce of c_part[:, b, :]
        const int k = t & 15, s = t >> 4;
        float a = 0.f;
        for (int bk = s; bk < NBLK; bk += 16)    // 37 iters
            a += c_part[bk * (B_DIM * K_DIM) + b * K_DIM + k];
        red16[s][k] = a;
    }
    __syncthreads();
    if (t < K_DIM) {
        float v = 0.f;
#pragma unroll
        for (int s = 0; s < 16; s++) v += red16[s][t];
        cb[t] = v;
    }
    __syncthreads();

    {   // layer 1: 16 -> 256, relu
        float acc = be1[t];
#pragma unroll
        for (int k = 0; k < K_DIM; k++)
            acc = fmaf(cb[k], We1[k * E_DIM + t], acc);
        hE[t] = fmaxf(acc, 0.f);
    }
    __syncthreads();

    {   // layer 2: 256 -> 64, split across 4 partial groups
        const int o = t & 63, part = t >> 6;
        float acc = 0.f;
        const int e0 = part * 64;
#pragma unroll 8
        for (int e = e0; e < e0 + 64; e++)
            acc = fmaf(hE[e], We2[e * (2 * Z_DIM) + o], acc);
        red[t] = acc;
        __syncthreads();
        if (part == 0) {
            float r = (red[o] + red[o + 64]) + (red[o + 128] + red[o + 192]) + be2[o];
            if (o < Z_DIM) out[b * Z_DIM + o] = r;                            // mu
            else           out[B_DIM * Z_DIM + b * Z_DIM + (o - Z_DIM)] = r;  // logvar
        }
    }
}

// ---------------------------------------------------------------------------
extern "C" void kernel_launch(void* const* d_in, const int* in_sizes, int n_in,
                              void* d_out, int out_size)
{
    const float* x    = (const float*)d_in[0];
    const int*   mask = (const int*)  d_in[1];
    const float* fe   = (const float*)d_in[2];
    const float* fb   = (const float*)d_in[3];
    const float* W1   = (const float*)d_in[4];
    const float* b1   = (const float*)d_in[5];
    const float* W2   = (const float*)d_in[6];
    const float* b2   = (const float*)d_in[7];
    const float* We1  = (const float*)d_in[8];
    const float* be1  = (const float*)d_in[9];
    const float* We2  = (const float*)d_in[10];
    const float* be2  = (const float*)d_in[11];
    float* out = (float*)d_out;

    k_main<<<NBLK, 128>>>(x, mask, W1, W2, b2, fe, fb, b1);
    k_enc <<<B_DIM, 256>>>(We1, be1, We2, be2, out);
}

// round 14
// speedup vs baseline: 1.4349x; 1.4349x over previous
#include <cuda_runtime.h>
#include <cstdint>

#define D_DIM 25000
#define B_DIM 64
#define K_DIM 16
#define H_DIM 128
#define E_DIM 256
#define Z_DIM 32

#define NBLK   592              // 148 SMs x 4 CTAs -> one wave
#define CHUNKS 3125             // 8 d's per chunk

// ---- scratch (device globals; no allocations allowed) ----
__device__ float g_buf[D_DIM * H_DIM];          // 12.8 MB: g[d][j]
__device__ float c_part[NBLK * B_DIM * K_DIM];  // per-block partial pooled c

// pack two fp32 -> bf16x2 {lo=a, hi=b}
__device__ __forceinline__ unsigned pkbf16(float a, float b) {
    unsigned r;
    asm("cvt.rn.bf16x2.f32 %0, %1, %2;" : "=r"(r) : "f"(b), "f"(a));
    return r;
}
__device__ __forceinline__ float bflo(unsigned p) { return __uint_as_float(p << 16); }
__device__ __forceinline__ float bfhi(unsigned p) { return __uint_as_float(p & 0xffff0000u); }
__device__ __forceinline__ unsigned relu2(unsigned a) {
    unsigned r;
    asm("max.bf16x2 %0, %1, %2;" : "=r"(r) : "r"(a), "r"(0u));
    return r;
}

#define MMA(C, a0, a1, a2, a3, b0, b1)                                     \
    asm("mma.sync.aligned.m16n8k16.row.col.f32.bf16.bf16.f32 "             \
        "{%0,%1,%2,%3}, {%4,%5,%6,%7}, {%8,%9}, {%0,%1,%2,%3};"            \
        : "+f"((C)[0]), "+f"((C)[1]), "+f"((C)[2]), "+f"((C)[3])           \
        : "r"(a0), "r"(a1), "r"(a2), "r"(a3), "r"(b0), "r"(b1))

// ---------------------------------------------------------------------------
// Kernel 1: g[d][j] = b1[j] + fb[d]*W1[17][j] + sum_i fe[d][i]*W1[1+i][j]
// 625 blocks x 40 d's. W1 rows 1..17 + b1 staged to smem ONCE per block
// (kills the 112 MB W1 re-read that made the old k_g L1-bound).
// Per 8-d group: stage fe/fb, each thread computes 4 (d, j) outputs with
// each W1 LDS reused across 4 d's.
// ---------------------------------------------------------------------------
__global__ __launch_bounds__(256)
void k_g(const float* __restrict__ fe, const float* __restrict__ fb,
         const float* __restrict__ W1, const float* __restrict__ b1)
{
    __shared__ __align__(16) float W1s[17 * H_DIM];  // rows 1..17 (17 at idx 16)
    __shared__ __align__(16) float b1s[H_DIM];
    __shared__ __align__(16) float fes[8 * K_DIM];
    __shared__ float fbs[8];

    const int t = threadIdx.x;
    for (int i = t; i < 17 * H_DIM; i += 256) W1s[i] = W1[H_DIM + i];
    if (t < H_DIM) b1s[t] = b1[t];

    const int j  = t & 127;
    const int dh = t >> 7;           // 0/1: which 4-d half of the group
    const int d_base = blockIdx.x * 40;

    __syncthreads();

    for (int gi = 0; gi < 5; gi++) {
        const int d0 = d_base + gi * 8;
        if (t < 128)            fes[t] = fe[d0 * K_DIM + t];
        else if (t < 136)       fbs[t - 128] = fb[d0 + t - 128];
        __syncthreads();

        float acc[4];
        const float* frow = fes + dh * 4 * K_DIM;
#pragma unroll
        for (int dd = 0; dd < 4; dd++)
            acc[dd] = b1s[j] + fbs[dh * 4 + dd] * W1s[16 * H_DIM + j];
#pragma unroll
        for (int i = 0; i < K_DIM; i++) {
            const float w = W1s[i * H_DIM + j];
#pragma unroll
            for (int dd = 0; dd < 4; dd++)
                acc[dd] = fmaf(frow[dd * K_DIM + i], w, acc[dd]);
        }
#pragma unroll
        for (int dd = 0; dd < 4; dd++)
            g_buf[(d0 + dh * 4 + dd) * H_DIM + j] = acc[dd];
        __syncthreads();
    }
}

// ---------------------------------------------------------------------------
// Kernel 2: main, tensor-core stage-2 (exact R9 structure, proven ~46us).
// Block = 128 thr = 4 warps. Warp w owns batches [16w,16w+16); warps share d.
// A[16 b x 128 j] built in-fragment: h = relu(x*w0 + g) (relu in bf16x2).
// 4 MMAs per ks: Ca += a*W2hi (2 n-halves), Cb += a*W2lo (compensation).
// ---------------------------------------------------------------------------
__global__ __launch_bounds__(128, 4)
void k_main(const float* __restrict__ x, const int* __restrict__ mask,
            const float* __restrict__ W1, const float* __restrict__ W2,
            const float* __restrict__ b2)
{
    __shared__ __align__(16) float gs[8 * H_DIM];   // 4 KB g rows for chunk
    __shared__ __align__(16) float xs[8][B_DIM];    // 2 KB
    __shared__ __align__(16) float ms[8][B_DIM];    // 2 KB
    __shared__ __align__(16) float w0s[H_DIM];
    __shared__ __align__(16) uint2 wloS[16 * 32];   // W2-lo frags, 4 KB

    const int t    = threadIdx.x;
    const int lane = t & 31;
    const int wrp  = t >> 5;
    const int g_l  = lane >> 2;     // 0..7  (row group)
    const int tt   = lane & 3;      // 0..3  (thread-in-group)
    const int bg   = wrp * 16;      // batch base of this warp

    if (t < H_DIM) w0s[t] = W1[t];

    // W2 fragments: hi in regs (all warps), lo into smem table (warp 0)
    unsigned whi[8][2][2];
#pragma unroll
    for (int ks = 0; ks < 8; ks++) {
#pragma unroll
        for (int nh = 0; nh < 2; nh++) {
            const int j0 = ks * 16 + 2 * tt;
            const int n  = nh * 8 + g_l;
            float w00 = W2[(j0    ) * K_DIM + n];
            float w01 = W2[(j0 + 1) * K_DIM + n];
            float w10 = W2[(j0 + 8) * K_DIM + n];
            float w11 = W2[(j0 + 9) * K_DIM + n];
            unsigned h0 = pkbf16(w00, w01);
            unsigned h1 = pkbf16(w10, w11);
            whi[ks][nh][0] = h0;
            whi[ks][nh][1] = h1;
            if (wrp == 0) {
                unsigned l0 = pkbf16(w00 - bflo(h0), w01 - bfhi(h0));
                unsigned l1 = pkbf16(w10 - bflo(h1), w11 - bfhi(h1));
                wloS[(ks * 2 + nh) * 32 + lane] = make_uint2(l0, l1);
            }
        }
    }
    const float b2r0 = b2[2 * tt],     b2r1 = b2[2 * tt + 1];
    const float b2r2 = b2[8 + 2 * tt], b2r3 = b2[8 + 2 * tt + 1];

    float acc[8];
#pragma unroll
    for (int i = 0; i < 8; i++) acc[i] = 0.f;

    __syncthreads();

    // contiguous balanced chunk partition: 3125 = 165*6 + 427*5
    int cnt, base;
    if (blockIdx.x < 165) { cnt = 6; base = blockIdx.x * 6; }
    else                  { cnt = 5; base = 990 + (blockIdx.x - 165) * 5; }

    for (int ci = 0; ci < cnt; ci++) {
        const int d0 = (base + ci) * 8;

        // cooperative staging for 8 d's
        {
            const float4* src = (const float4*)(g_buf + d0 * H_DIM); // 256 float4
            ((float4*)gs)[t]       = src[t];
            ((float4*)gs)[t + 128] = src[t + 128];
            for (int i = t; i < 512; i += 128) {
                int b = i >> 3, qq = i & 7;
                int gi = b * D_DIM + d0 + qq;
                xs[qq][b] = x[gi];
                ms[qq][b] = (float)mask[gi];
            }
        }
        __syncthreads();

        for (int dq = 0; dq < 8; dq++) {
            const float* gsd = gs + dq * H_DIM;
            const float x0 = xs[dq][bg + g_l];
            const float x1 = xs[dq][bg + g_l + 8];
            const float m0 = ms[dq][bg + g_l];
            const float m1 = ms[dq][bg + g_l + 8];

            float Ca[2][4], Cb[2][4];
#pragma unroll
            for (int nh = 0; nh < 2; nh++)
#pragma unroll
                for (int i = 0; i < 4; i++) { Ca[nh][i] = 0.f; Cb[nh][i] = 0.f; }

#pragma unroll
            for (int ks = 0; ks < 8; ks++) {
                const int j0 = ks * 16 + 2 * tt;
                const float2 gA = *(const float2*)(gsd + j0);
                const float2 gB = *(const float2*)(gsd + j0 + 8);
                const float2 wA = *(const float2*)(w0s + j0);
                const float2 wB = *(const float2*)(w0s + j0 + 8);

                const float h00 = fmaf(x0, wA.x, gA.x);
                const float h01 = fmaf(x0, wA.y, gA.y);
                const float h02 = fmaf(x0, wB.x, gB.x);
                const float h03 = fmaf(x0, wB.y, gB.y);
                const float h10 = fmaf(x1, wA.x, gA.x);
                const float h11 = fmaf(x1, wA.y, gA.y);
                const float h12 = fmaf(x1, wB.x, gB.x);
                const float h13 = fmaf(x1, wB.y, gB.y);

                const unsigned a0 = relu2(pkbf16(h00, h01));
                const unsigned a1 = relu2(pkbf16(h10, h11));
                const unsigned a2 = relu2(pkbf16(h02, h03));
                const unsigned a3 = relu2(pkbf16(h12, h13));

#pragma unroll
                for (int nh = 0; nh < 2; nh++) {
                    const uint2 wlo = wloS[(ks * 2 + nh) * 32 + lane];
                    MMA(Ca[nh], a0, a1, a2, a3, whi[ks][nh][0], whi[ks][nh][1]);
                    MMA(Cb[nh], a0, a1, a2, a3, wlo.x, wlo.y);
                }
            }

            // epilogue: relu(s + b2) * mask, pooled
            acc[0] = fmaf(m0, fmaxf(Ca[0][0] + Cb[0][0] + b2r0, 0.f), acc[0]);
            acc[1] = fmaf(m0, fmaxf(Ca[0][1] + Cb[0][1] + b2r1, 0.f), acc[1]);
            acc[2] = fmaf(m1, fmaxf(Ca[0][2] + Cb[0][2] + b2r0, 0.f), acc[2]);
            acc[3] = fmaf(m1, fmaxf(Ca[0][3] + Cb[0][3] + b2r1, 0.f), acc[3]);
            acc[4] = fmaf(m0, fmaxf(Ca[1][0] + Cb[1][0] + b2r2, 0.f), acc[4]);
            acc[5] = fmaf(m0, fmaxf(Ca[1][1] + Cb[1][1] + b2r3, 0.f), acc[5]);
            acc[6] = fmaf(m1, fmaxf(Ca[1][2] + Cb[1][2] + b2r2, 0.f), acc[6]);
            acc[7] = fmaf(m1, fmaxf(Ca[1][3] + Cb[1][3] + b2r3, 0.f), acc[7]);
        }
        __syncthreads();   // protect gs/xs/ms before next staging
    }

    // per-block partial store; warps own disjoint batches
    float* cp = c_part + blockIdx.x * (B_DIM * K_DIM);
    const int b0r = bg + g_l, b1r = bg + g_l + 8;
    cp[b0r * K_DIM +     2 * tt    ] = acc[0];
    cp[b0r * K_DIM +     2 * tt + 1] = acc[1];
    cp[b1r * K_DIM +     2 * tt    ] = acc[2];
    cp[b1r * K_DIM +     2 * tt + 1] = acc[3];
    cp[b0r * K_DIM + 8 + 2 * tt    ] = acc[4];
    cp[b0r * K_DIM + 8 + 2 * tt + 1] = acc[5];
    cp[b1r * K_DIM + 8 + 2 * tt    ] = acc[6];
    cp[b1r * K_DIM + 8 + 2 * tt + 1] = acc[7];
}

// ---------------------------------------------------------------------------
// Kernel 3: fused partial-reduce + encoder MLP + split (mu||logvar) output.
// Reduce uses 4 independent accumulators -> 4 DRAM loads in flight
// (old version was 1-deep: 37 x raw DRAM latency = 16us).
// ---------------------------------------------------------------------------
__global__ void k_enc(const float* __restrict__ We1, const float* __restrict__ be1,
                      const float* __restrict__ We2, const float* __restrict__ be2,
                      float* __restrict__ out)
{
    __shared__ float red16[16][17];
    __shared__ float cb[K_DIM];
    __shared__ float hE[E_DIM];
    __shared__ float red[256];
    const int b = blockIdx.x, t = threadIdx.x;   // 256 threads

    {   // deterministic reduce of c_part[:, b, :]; 592 partials = 16 strides x 37
        const int k = t & 15, s = t >> 4;
        const int off = b * K_DIM + k;
        float a0 = 0.f, a1 = 0.f, a2 = 0.f, a3 = 0.f;
#pragma unroll
        for (int m = 0; m < 9; m++) {            // 4 x 9 = 36 terms, MLP=4
            const int bk = s + 64 * m;
            a0 += c_part[(bk     ) * (B_DIM * K_DIM) + off];
            a1 += c_part[(bk + 16) * (B_DIM * K_DIM) + off];
            a2 += c_part[(bk + 32) * (B_DIM * K_DIM) + off];
            a3 += c_part[(bk + 48) * (B_DIM * K_DIM) + off];
        }
        a0 += c_part[(s + 576) * (B_DIM * K_DIM) + off];   // 37th term
        red16[s][k] = (a0 + a1) + (a2 + a3);
    }
    __syncthreads();
    if (t < K_DIM) {
        float v = 0.f;
#pragma unroll
        for (int s = 0; s < 16; s++) v += red16[s][t];
        cb[t] = v;
    }
    __syncthreads();

    {   // layer 1: 16 -> 256, relu
        float acc = be1[t];
#pragma unroll
        for (int k = 0; k < K_DIM; k++)
            acc = fmaf(cb[k], We1[k * E_DIM + t], acc);
        hE[t] = fmaxf(acc, 0.f);
    }
    __syncthreads();

    {   // layer 2: 256 -> 64, split across 4 partial groups
        const int o = t & 63, part = t >> 6;
        float acc = 0.f;
        const int e0 = part * 64;
#pragma unroll 8
        for (int e = e0; e < e0 + 64; e++)
            acc = fmaf(hE[e], We2[e * (2 * Z_DIM) + o], acc);
        red[t] = acc;
        __syncthreads();
        if (part == 0) {
            float r = (red[o] + red[o + 64]) + (red[o + 128] + red[o + 192]) + be2[o];
            if (o < Z_DIM) out[b * Z_DIM + o] = r;                            // mu
            else           out[B_DIM * Z_DIM + b * Z_DIM + (o - Z_DIM)] = r;  // logvar
        }
    }
}

// ---------------------------------------------------------------------------
extern "C" void kernel_launch(void* const* d_in, const int* in_sizes, int n_in,
                              void* d_out, int out_size)
{
    const float* x    = (const float*)d_in[0];
    const int*   mask = (const int*)  d_in[1];
    const float* fe   = (const float*)d_in[2];
    const float* fb   = (const float*)d_in[3];
    const float* W1   = (const float*)d_in[4];
    const float* b1   = (const float*)d_in[5];
    const float* W2   = (const float*)d_in[6];
    const float* b2   = (const float*)d_in[7];
    const float* We1  = (const float*)d_in[8];
    const float* be1  = (const float*)d_in[9];
    const float* We2  = (const float*)d_in[10];
    const float* be2  = (const float*)d_in[11];
    float* out = (float*)d_out;

    k_g   <<<625, 256>>>(fe, fb, W1, b1);
    k_main<<<NBLK, 128>>>(x, mask, W1, W2, b2);
    k_enc <<<B_DIM, 256>>>(We1, be1, We2, be2, out);
}

// round 15
// speedup vs baseline: 1.6240x; 1.1318x over previous
#include <cuda_runtime.h>
#include <cstdint>

#define D_DIM 25000
#define B_DIM 64
#define K_DIM 16
#define H_DIM 128
#define E_DIM 256
#define Z_DIM 32

#define NBLK   592              // 148 SMs x 4 CTAs -> one wave
#define CHUNKS 3125             // 8 d's per chunk

// ---- scratch (device globals; no allocations allowed) ----
__device__ float g_buf[D_DIM * H_DIM];          // 12.8 MB: g[d][j]
__device__ float c_part[NBLK * B_DIM * K_DIM];  // per-block partial pooled c

// pack two fp32 -> bf16x2 {lo=a, hi=b}
__device__ __forceinline__ unsigned pkbf16(float a, float b) {
    unsigned r;
    asm("cvt.rn.bf16x2.f32 %0, %1, %2;" : "=r"(r) : "f"(b), "f"(a));
    return r;
}
__device__ __forceinline__ float bflo(unsigned p) { return __uint_as_float(p << 16); }
__device__ __forceinline__ float bfhi(unsigned p) { return __uint_as_float(p & 0xffff0000u); }
__device__ __forceinline__ unsigned relu2(unsigned a) {
    unsigned r;
    asm("max.bf16x2 %0, %1, %2;" : "=r"(r) : "r"(a), "r"(0u));
    return r;
}

#define MMA(C, a0, a1, a2, a3, b0, b1)                                     \
    asm("mma.sync.aligned.m16n8k16.row.col.f32.bf16.bf16.f32 "             \
        "{%0,%1,%2,%3}, {%4,%5,%6,%7}, {%8,%9}, {%0,%1,%2,%3};"            \
        : "+f"((C)[0]), "+f"((C)[1]), "+f"((C)[2]), "+f"((C)[3])           \
        : "r"(a0), "r"(a1), "r"(a2), "r"(a3), "r"(b0), "r"(b1))

#define CP16(dst_u32, src_ptr)                                             \
    asm volatile("cp.async.cg.shared.global [%0], [%1], 16;"               \
                 :: "r"(dst_u32), "l"(src_ptr))
#define CP_COMMIT() asm volatile("cp.async.commit_group;" ::: "memory")
#define CP_WAIT1()  asm volatile("cp.async.wait_group 1;"  ::: "memory")
#define CP_WAIT0()  asm volatile("cp.async.wait_group 0;"  ::: "memory")

__device__ __forceinline__ unsigned sm_u32(const void* p) {
    return (unsigned)__cvta_generic_to_shared(p);
}

// ---------------------------------------------------------------------------
// Kernel 1: g[d][j] = b1[j] + fb[d]*W1[17][j] + sum_i fe[d][i]*W1[1+i][j]
// 3125 blocks x 8 d's, SINGLE barrier. W1 column j read straight to regs
// (coalesced; L2-broadcast across blocks). Thread computes 4 (d, j) outputs.
// ---------------------------------------------------------------------------
__global__ __launch_bounds__(256)
void k_g(const float* __restrict__ fe, const float* __restrict__ fb,
         const float* __restrict__ W1, const float* __restrict__ b1)
{
    __shared__ __align__(16) float fes[8 * K_DIM];
    __shared__ float fbs[8];

    const int t  = threadIdx.x;
    const int d0 = blockIdx.x * 8;
    if (t < 128)       fes[t] = fe[d0 * K_DIM + t];
    else if (t < 136)  fbs[t - 128] = fb[d0 + t - 128];

    const int j  = t & 127;
    const int dh = t >> 7;          // 0/1: which 4-d half

    float w[17];
#pragma unroll
    for (int i = 0; i < 17; i++) w[i] = W1[(1 + i) * H_DIM + j];
    const float bj = b1[j];

    __syncthreads();

    const float* frow = fes + dh * 4 * K_DIM;
    float acc[4];
#pragma unroll
    for (int dd = 0; dd < 4; dd++) acc[dd] = fmaf(fbs[dh * 4 + dd], w[16], bj);
#pragma unroll
    for (int i = 0; i < 16; i++) {
#pragma unroll
        for (int dd = 0; dd < 4; dd++)
            acc[dd] = fmaf(frow[dd * K_DIM + i], w[i], acc[dd]);
    }
#pragma unroll
    for (int dd = 0; dd < 4; dd++)
        g_buf[(d0 + dh * 4 + dd) * H_DIM + j] = acc[dd];
}

// ---------------------------------------------------------------------------
// Kernel 2: main, tensor-core stage-2 with DOUBLE-BUFFERED cp.async staging.
// Block = 128 thr = 4 warps. Warp w owns batches [16w,16w+16); warps share d.
// Per 8-d chunk: prefetch next chunk's g/x/mask while computing current.
// 4 MMAs per ks: Ca += a*W2hi (2 n-halves), Cb += a*W2lo (compensation).
// ---------------------------------------------------------------------------
__global__ __launch_bounds__(128, 4)
void k_main(const float* __restrict__ x, const int* __restrict__ mask,
            const float* __restrict__ W1, const float* __restrict__ W2,
            const float* __restrict__ b2)
{
    __shared__ __align__(16) float gs [2][8 * H_DIM];   // 2 x 4 KB
    __shared__ __align__(16) float xs [2][B_DIM][8];    // 2 x 2 KB (b-major)
    __shared__ __align__(16) int   msI[2][B_DIM][8];    // 2 x 2 KB (raw int)
    __shared__ __align__(16) float w0s[H_DIM];
    __shared__ __align__(16) uint2 wloS[16 * 32];       // W2-lo frags, 4 KB

    const int t    = threadIdx.x;
    const int lane = t & 31;
    const int wrp  = t >> 5;
    const int g_l  = lane >> 2;     // 0..7  (row group)
    const int tt   = lane & 3;      // 0..3  (thread-in-group)
    const int bg   = wrp * 16;      // batch base of this warp

    if (t < H_DIM) w0s[t] = W1[t];

    // W2 fragments: hi in regs (all warps), lo into smem table (warp 0)
    unsigned whi[8][2][2];
#pragma unroll
    for (int ks = 0; ks < 8; ks++) {
#pragma unroll
        for (int nh = 0; nh < 2; nh++) {
            const int j0 = ks * 16 + 2 * tt;
            const int n  = nh * 8 + g_l;
            float w00 = W2[(j0    ) * K_DIM + n];
            float w01 = W2[(j0 + 1) * K_DIM + n];
            float w10 = W2[(j0 + 8) * K_DIM + n];
            float w11 = W2[(j0 + 9) * K_DIM + n];
            unsigned h0 = pkbf16(w00, w01);
            unsigned h1 = pkbf16(w10, w11);
            whi[ks][nh][0] = h0;
            whi[ks][nh][1] = h1;
            if (wrp == 0) {
                unsigned l0 = pkbf16(w00 - bflo(h0), w01 - bfhi(h0));
                unsigned l1 = pkbf16(w10 - bflo(h1), w11 - bfhi(h1));
                wloS[(ks * 2 + nh) * 32 + lane] = make_uint2(l0, l1);
            }
        }
    }
    const float b2r0 = b2[2 * tt],     b2r1 = b2[2 * tt + 1];
    const float b2r2 = b2[8 + 2 * tt], b2r3 = b2[8 + 2 * tt + 1];

    float acc[8];
#pragma unroll
    for (int i = 0; i < 8; i++) acc[i] = 0.f;

    // per-thread prefetch addressing (4 x 16B per chunk)
    const int pb   = t >> 1;        // 0..63 batch for x/mask copy
    const int phf  = t & 1;         // 0/1 half (4 d's)
    const unsigned gdst0 = sm_u32(&gs[0][0]) + (unsigned)t * 16;
    const unsigned gdst1 = sm_u32(&gs[1][0]) + (unsigned)t * 16;
    const unsigned xdst0 = sm_u32(&xs[0][pb][phf * 4]);
    const unsigned xdst1 = sm_u32(&xs[1][pb][phf * 4]);
    const unsigned mdst0 = sm_u32(&msI[0][pb][phf * 4]);
    const unsigned mdst1 = sm_u32(&msI[1][pb][phf * 4]);

    // contiguous balanced chunk partition: 3125 = 165*6 + 427*5
    int cnt, base;
    if (blockIdx.x < 165) { cnt = 6; base = blockIdx.x * 6; }
    else                  { cnt = 5; base = 990 + (blockIdx.x - 165) * 5; }

#define PREFETCH(buf, dd0)                                                   \
    do {                                                                     \
        const char* gsrc = (const char*)(g_buf + (dd0) * H_DIM) + t * 16;    \
        CP16((buf) ? gdst1 : gdst0, gsrc);                                   \
        CP16(((buf) ? gdst1 : gdst0) + 2048, gsrc + 2048);                   \
        CP16((buf) ? xdst1 : xdst0, x    + pb * D_DIM + (dd0) + phf * 4);    \
        CP16((buf) ? mdst1 : mdst0, mask + pb * D_DIM + (dd0) + phf * 4);    \
    } while (0)

    PREFETCH(0, base * 8);
    CP_COMMIT();
    __syncthreads();   // also covers w0s/wloS staging

    for (int ci = 0; ci < cnt; ci++) {
        const int cur = ci & 1;
        if (ci + 1 < cnt) {
            PREFETCH(cur ^ 1, (base + ci + 1) * 8);
            CP_COMMIT();
            CP_WAIT1();
        } else {
            CP_WAIT0();
        }
        __syncthreads();   // current buffer visible to all warps

        for (int dq = 0; dq < 8; dq++) {
            const float* gsd = gs[cur] + dq * H_DIM;
            const float x0 = xs[cur][bg + g_l][dq];
            const float x1 = xs[cur][bg + g_l + 8][dq];

            float Ca[2][4], Cb[2][4];
#pragma unroll
            for (int nh = 0; nh < 2; nh++)
#pragma unroll
                for (int i = 0; i < 4; i++) { Ca[nh][i] = 0.f; Cb[nh][i] = 0.f; }

#pragma unroll
            for (int ks = 0; ks < 8; ks++) {
                const int j0 = ks * 16 + 2 * tt;
                const float2 gA = *(const float2*)(gsd + j0);
                const float2 gB = *(const float2*)(gsd + j0 + 8);
                const float2 wA = *(const float2*)(w0s + j0);
                const float2 wB = *(const float2*)(w0s + j0 + 8);

                const float h00 = fmaf(x0, wA.x, gA.x);
                const float h01 = fmaf(x0, wA.y, gA.y);
                const float h02 = fmaf(x0, wB.x, gB.x);
                const float h03 = fmaf(x0, wB.y, gB.y);
                const float h10 = fmaf(x1, wA.x, gA.x);
                const float h11 = fmaf(x1, wA.y, gA.y);
                const float h12 = fmaf(x1, wB.x, gB.x);
                const float h13 = fmaf(x1, wB.y, gB.y);

                const unsigned a0 = relu2(pkbf16(h00, h01));
                const unsigned a1 = relu2(pkbf16(h10, h11));
                const unsigned a2 = relu2(pkbf16(h02, h03));
                const unsigned a3 = relu2(pkbf16(h12, h13));

#pragma unroll
                for (int nh = 0; nh < 2; nh++) {
                    const uint2 wlo = wloS[(ks * 2 + nh) * 32 + lane];
                    MMA(Ca[nh], a0, a1, a2, a3, whi[ks][nh][0], whi[ks][nh][1]);
                    MMA(Cb[nh], a0, a1, a2, a3, wlo.x, wlo.y);
                }
            }

            // epilogue: relu(s + b2) * mask, pooled
            const float m0 = (float)msI[cur][bg + g_l][dq];
            const float m1 = (float)msI[cur][bg + g_l + 8][dq];
            acc[0] = fmaf(m0, fmaxf(Ca[0][0] + Cb[0][0] + b2r0, 0.f), acc[0]);
            acc[1] = fmaf(m0, fmaxf(Ca[0][1] + Cb[0][1] + b2r1, 0.f), acc[1]);
            acc[2] = fmaf(m1, fmaxf(Ca[0][2] + Cb[0][2] + b2r0, 0.f), acc[2]);
            acc[3] = fmaf(m1, fmaxf(Ca[0][3] + Cb[0][3] + b2r1, 0.f), acc[3]);
            acc[4] = fmaf(m0, fmaxf(Ca[1][0] + Cb[1][0] + b2r2, 0.f), acc[4]);
            acc[5] = fmaf(m0, fmaxf(Ca[1][1] + Cb[1][1] + b2r3, 0.f), acc[5]);
            acc[6] = fmaf(m1, fmaxf(Ca[1][2] + Cb[1][2] + b2r2, 0.f), acc[6]);
            acc[7] = fmaf(m1, fmaxf(Ca[1][3] + Cb[1][3] + b2r3, 0.f), acc[7]);
        }
        __syncthreads();   // all warps done with 'cur' before it is re-prefetched
    }

    // per-block partial store; warps own disjoint batches
    float* cp = c_part + blockIdx.x * (B_DIM * K_DIM);
    const int b0r = bg + g_l, b1r = bg + g_l + 8;
    cp[b0r * K_DIM +     2 * tt    ] = acc[0];
    cp[b0r * K_DIM +     2 * tt + 1] = acc[1];
    cp[b1r * K_DIM +     2 * tt    ] = acc[2];
    cp[b1r * K_DIM +     2 * tt + 1] = acc[3];
    cp[b0r * K_DIM + 8 + 2 * tt    ] = acc[4];
    cp[b0r * K_DIM + 8 + 2 * tt + 1] = acc[5];
    cp[b1r * K_DIM + 8 + 2 * tt    ] = acc[6];
    cp[b1r * K_DIM + 8 + 2 * tt + 1] = acc[7];
#undef PREFETCH
}

// ---------------------------------------------------------------------------
// Kernel 3: fused partial-reduce + encoder MLP + split (mu||logvar) output.
// ---------------------------------------------------------------------------
__global__ void k_enc(const float* __restrict__ We1, const float* __restrict__ be1,
                      const float* __restrict__ We2, const float* __restrict__ be2,
                      float* __restrict__ out)
{
    __shared__ float red16[16][17];
    __shared__ float cb[K_DIM];
    __shared__ float hE[E_DIM];
    __shared__ float red[256];
    const int b = blockIdx.x, t = threadIdx.x;   // 256 threads

    {   // deterministic reduce of c_part[:, b, :]; 592 partials, 4 loads in flight
        const int k = t & 15, s = t >> 4;
        const int off = b * K_DIM + k;
        float a0 = 0.f, a1 = 0.f, a2 = 0.f, a3 = 0.f;
#pragma unroll
        for (int m = 0; m < 9; m++) {
            const int bk = s + 64 * m;
            a0 += c_part[(bk     ) * (B_DIM * K_DIM) + off];
            a1 += c_part[(bk + 16) * (B_DIM * K_DIM) + off];
            a2 += c_part[(bk + 32) * (B_DIM * K_DIM) + off];
            a3 += c_part[(bk + 48) * (B_DIM * K_DIM) + off];
        }
        a0 += c_part[(s + 576) * (B_DIM * K_DIM) + off];
        red16[s][k] = (a0 + a1) + (a2 + a3);
    }
    __syncthreads();
    if (t < K_DIM) {
        float v = 0.f;
#pragma unroll
        for (int s = 0; s < 16; s++) v += red16[s][t];
        cb[t] = v;
    }
    __syncthreads();

    {   // layer 1: 16 -> 256, relu
        float acc = be1[t];
#pragma unroll
        for (int k = 0; k < K_DIM; k++)
            acc = fmaf(cb[k], We1[k * E_DIM + t], acc);
        hE[t] = fmaxf(acc, 0.f);
    }
    __syncthreads();

    {   // layer 2: 256 -> 64, split across 4 partial groups
        const int o = t & 63, part = t >> 6;
        float acc = 0.f;
        const int e0 = part * 64;
#pragma unroll 8
        for (int e = e0; e < e0 + 64; e++)
            acc = fmaf(hE[e], We2[e * (2 * Z_DIM) + o], acc);
        red[t] = acc;
        __syncthreads();
        if (part == 0) {
            float r = (red[o] + red[o + 64]) + (red[o + 128] + red[o + 192]) + be2[o];
            if (o < Z_DIM) out[b * Z_DIM + o] = r;                            // mu
            else           out[B_DIM * Z_DIM + b * Z_DIM + (o - Z_DIM)] = r;  // logvar
        }
    }
}

// ---------------------------------------------------------------------------
extern "C" void kernel_launch(void* const* d_in, const int* in_sizes, int n_in,
                              void* d_out, int out_size)
{
    const float* x    = (const float*)d_in[0];
    const int*   mask = (const int*)  d_in[1];
    const float* fe   = (const float*)d_in[2];
    const float* fb   = (const float*)d_in[3];
    const float* W1   = (const float*)d_in[4];
    const float* b1   = (const float*)d_in[5];
    const float* W2   = (const float*)d_in[6];
    const float* b2   = (const float*)d_in[7];
    const float* We1  = (const float*)d_in[8];
    const float* be1  = (const float*)d_in[9];
    const float* We2  = (const float*)d_in[10];
    const float* be2  = (const float*)d_in[11];
    float* out = (float*)d_out;

    k_g   <<<CHUNKS, 256>>>(fe, fb, W1, b1);
    k_main<<<NBLK, 128>>>(x, mask, W1, W2, b2);
    k_enc <<<B_DIM, 256>>>(We1, be1, We2, be2, out);
}